// round 14
// baseline (speedup 1.0000x reference)
#include <cuda_runtime.h>
#include <float.h>

// -------- scratch (no allocations; zero-init; ce_kernel resets) --------
#define MAXS 32768
#define MAXC 65536
#define MAXB 128                                    // max scan blocks (MAXS/256)
__device__ int                g_off     [MAXS + 1]; // exclusive prefix sum + sentinel
__device__ int                g_chunkseg[MAXC];     // chunk -> containing segment
__device__ int                g_tilesum [MAXB];     // per-scan-block scope totals
__device__ unsigned long long g_tden[MAXS];         // fixed-point (2^34) Σ e^t
__device__ unsigned long long g_msum[MAXS];         // fixed-point Σ e^m
__device__ unsigned long long g_dot [MAXS];         // fixed-point Σ e^t * m
__device__ unsigned long long g_acc;                // fixed-point global Σ ce
__device__ unsigned int       g_scnt;               // scan phase-1 arrivals
__device__ unsigned int       g_mapcnt;             // map completion arrivals
__device__ unsigned int       g_done;               // finished-block counter (ce)

#define SCALE     17179869184.0   // 2^34
#define INV_SCALE 0x1p-34f        // exact power-of-two

__device__ __forceinline__ unsigned int load_acquire_u32(const unsigned int* p) {
    unsigned int v;
    asm volatile("ld.global.acquire.gpu.b32 %0, [%1];" : "=r"(v) : "l"(p) : "memory");
    return v;
}

// ---- chunk load + exp (offset-independent) ----
__device__ __forceinline__ void load_exp_chunk(
    const float* __restrict__ means, const float* __restrict__ targets,
    int base, int lane, int N, float* e, float* w, float* d)
{
    if (base + 256 <= N) {
        const float4* tp = reinterpret_cast<const float4*>(targets);
        const float4* mp = reinterpret_cast<const float4*>(means);
        const int q = (base >> 2) + lane;
        float4 t0 = tp[q];       float4 t1 = tp[q + 32];
        float4 m0 = mp[q];       float4 m1 = mp[q + 32];
        float tt[8] = {t0.x,t0.y,t0.z,t0.w, t1.x,t1.y,t1.z,t1.w};
        float mm[8] = {m0.x,m0.y,m0.z,m0.w, m1.x,m1.y,m1.z,m1.w};
        #pragma unroll
        for (int j = 0; j < 8; ++j) {
            e[j] = __expf(tt[j]);
            w[j] = __expf(mm[j]);
            d[j] = e[j] * mm[j];
        }
    } else {
        const int pos0 = base + lane * 4;
        const int pos1 = base + 128 + lane * 4;
        #pragma unroll
        for (int j = 0; j < 8; ++j) {
            int p = (j < 4) ? (pos0 + j) : (pos1 + j - 4);
            float tv = (p < N) ? targets[p] : 0.f;
            float mv = (p < N) ? means[p]   : 0.f;
            e[j] = __expf(tv);
            w[j] = __expf(mv);
            d[j] = e[j] * mv;
        }
    }
}

// ============================================================
// Fused kernel (SINGLE WAVE — grid sized via occupancy API):
//   blocks [0,SB): scan scope (1 seg/thread) + fill chunk map
//   all blocks   : prefetch 1st chunk, ONE wait for map, then
//                  grid-stride bucket/prefetch pipeline
// ============================================================
__global__ void __launch_bounds__(256)
fused_kernel(const float* __restrict__ means,
             const float* __restrict__ targets,
             const int*   __restrict__ scope,
             int N, int S)
{
    const int tid  = threadIdx.x;
    const int lane = tid & 31;
    const int wid  = tid >> 5;          // 8 warps
    const int SB   = (S + 255) >> 8;    // scan blocks (<= MAXB)

    __shared__ int s_w[8];

    // ---------------- Phase A: scan + map (blocks < SB) ----------------
    if (blockIdx.x < SB) {
        const int b = blockIdx.x;
        const int s = b * 256 + tid;
        const int len = (s < S) ? scope[s] : 0;

        // block-wide exclusive scan of len
        int x = len;
        #pragma unroll
        for (int off = 1; off < 32; off <<= 1) {
            int y = __shfl_up_sync(0xffffffffu, x, off);
            if (lane >= off) x += y;
        }
        if (lane == 31) s_w[wid] = x;
        __syncthreads();
        if (wid == 0) {
            int w = (lane < 8) ? s_w[lane] : 0;
            #pragma unroll
            for (int off = 1; off < 8; off <<= 1) {
                int y = __shfl_up_sync(0xffffffffu, w, off);
                if (lane >= off) w += y;
            }
            if (lane < 8) s_w[lane] = w;
        }
        __syncthreads();

        const int intra = ((wid == 0) ? 0 : s_w[wid - 1]) + (x - len);
        const int btot  = s_w[7];

        if (tid == 0) {
            g_tilesum[b] = btot;
            __threadfence();
            atomicAdd(&g_scnt, 1u);
        }
        if (tid == 0) {
            while (load_acquire_u32(&g_scnt) < (unsigned int)SB) { __nanosleep(32); }
        }
        __syncthreads();

        int pre = 0;
        for (int j = 0; j < b; ++j) pre += g_tilesum[j];   // L1-broadcast reads

        if (s < S) {
            const int start = pre + intra;
            const int end   = start + len;
            g_off[s] = start;
            if (s == S - 1) g_off[S] = end;                 // sentinel (== N)
            for (int c = (start + 255) >> 8; (c << 8) < end; ++c)
                g_chunkseg[c] = s;
        }
        __syncthreads();
        if (tid == 0) {
            __threadfence();
            atomicAdd(&g_mapcnt, 1u);
        }
    }

    // ---------------- Phase B: streaming (all blocks) ----------------
    const int totalWarps = gridDim.x * 8;
    const int nChunks    = (N + 255) >> 8;

    int chunk = blockIdx.x * 8 + wid;
    bool has = (chunk < nChunks);

    float e[8], w[8], d[8];
    if (has) load_exp_chunk(means, targets, chunk << 8, lane, N, e, w, d);

    // ONE block-level wait for map completion (1 poller/block, acquire loads)
    if (tid == 0) {
        while (load_acquire_u32(&g_mapcnt) < (unsigned int)SB) { __nanosleep(32); }
    }
    __syncthreads();

    while (has) {
        const int base = chunk << 8;
        int s = g_chunkseg[chunk];

        const int pos0 = base + lane * 4;
        const int pos1 = base + 128 + lane * 4;
        const int last = min(base + 255, N - 1);

        int lower = g_off[s];
        for (;;) {
            const int next = g_off[s + 1];
            float a = 0.f, bb = 0.f, c = 0.f;
            #pragma unroll
            for (int j = 0; j < 8; ++j) {
                const int p = (j < 4) ? (pos0 + j) : (pos1 + j - 4);
                if (p >= lower && p < next) { a += e[j]; bb += w[j]; c += d[j]; }
            }
            #pragma unroll
            for (int o = 16; o; o >>= 1) {
                a  += __shfl_xor_sync(0xffffffffu, a,  o);
                bb += __shfl_xor_sync(0xffffffffu, bb, o);
                c  += __shfl_xor_sync(0xffffffffu, c,  o);
            }
            if (lane == 0) {
                atomicAdd(&g_tden[s], (unsigned long long)__double2ll_rn((double)a  * SCALE));
                atomicAdd(&g_msum[s], (unsigned long long)__double2ll_rn((double)bb * SCALE));
                atomicAdd(&g_dot [s], (unsigned long long)__double2ll_rn((double)c  * SCALE));
            }
            if (next > last) break;
            lower = next;
            ++s;
        }

        chunk += totalWarps;
        has = (chunk < nChunks);
        if (has) load_exp_chunk(means, targets, chunk << 8, lane, N, e, w, d);
    }
}

// ============================================================
// Kernel 2: per-segment CE (fp32) + deterministic reduce + reset
// ============================================================
__global__ void __launch_bounds__(256)
ce_kernel(float* __restrict__ out, int S)
{
    const int tid  = threadIdx.x;
    const int lane = tid & 31;
    const int wid  = tid >> 5;
    const int seg  = blockIdx.x * 256 + tid;

    float ce = 0.f;
    if (seg < S) {
        long long tdq = (long long)g_tden[seg];
        float td = __ll2float_rn(tdq);                                 // 2^34 scale cancels
        float ms = __ll2float_rn((long long)g_msum[seg]) * INV_SCALE;  // exact pow2 scale
        float dt = __ll2float_rn((long long)g_dot [seg]);
        if (tdq > 0) ce = dt / td - __logf(ms);
        g_tden[seg] = 0ull; g_msum[seg] = 0ull; g_dot[seg] = 0ull;     // reset for next replay
    }

    __shared__ float sm[8];
    float v = ce;
    #pragma unroll
    for (int o = 16; o; o >>= 1) v += __shfl_xor_sync(0xffffffffu, v, o);
    if (lane == 0) sm[wid] = v;
    __syncthreads();
    if (wid == 0) {
        v = (lane < 8) ? sm[lane] : 0.f;
        #pragma unroll
        for (int o = 4; o; o >>= 1) v += __shfl_xor_sync(0xffffffffu, v, o);
        if (lane == 0) {
            atomicAdd(&g_acc, (unsigned long long)__double2ll_rn((double)v * SCALE));
            __threadfence();
            unsigned int prev = atomicAdd(&g_done, 1u);
            if (prev == gridDim.x - 1) {
                unsigned long long tot = atomicAdd(&g_acc, 0ull);
                double sum = (double)(long long)tot / SCALE;
                out[0] = (float)(-sum / (double)S);
                g_acc    = 0ull;   // reset for next replay
                g_done   = 0u;
                g_scnt   = 0u;     // re-arm handshakes
                g_mapcnt = 0u;
                __threadfence();
            }
        }
    }
}

// ============================================================
extern "C" void kernel_launch(void* const* d_in, const int* in_sizes, int n_in,
                              void* d_out, int out_size)
{
    const float* means   = (const float*)d_in[0];
    const int*   scope   = (const int*)  d_in[1];
    const float* targets = (const float*)d_in[2];
    const int N = in_sizes[0];
    const int S = in_sizes[1];

    // single-wave grid: SMs x resident-blocks-per-SM (deterministic per device)
    int dev = 0;
    cudaGetDevice(&dev);
    int sms = 0;
    cudaDeviceGetAttribute(&sms, cudaDevAttrMultiProcessorCount, dev);
    int bpm = 0;
    cudaOccupancyMaxActiveBlocksPerMultiprocessor(&bpm, fused_kernel, 256, 0);
    if (sms <= 0) sms = 148;
    if (bpm <= 0) bpm = 1;

    const int SB       = (S + 255) >> 8;          // scan blocks needed
    const int nChB     = (N + 2047) >> 11;        // blocks if 1 chunk per warp
    int grid = sms * bpm;                         // exactly one wave
    if (grid > nChB) grid = nChB;                 // don't oversize
    if (grid < SB)   grid = SB;                   // scan blocks must all be resident

    fused_kernel<<<grid, 256>>>(means, targets, scope, N, S);
    ce_kernel<<<(S + 255) / 256, 256>>>((float*)d_out, S);
}

// round 15
// speedup vs baseline: 1.0649x; 1.0649x over previous
#include <cuda_runtime.h>
#include <float.h>

// -------- scratch (no allocations; zero-init; ce_kernel resets) --------
#define MAXS 32768
#define MAXC 65536
__device__ int                g_off     [MAXS + 1]; // exclusive prefix sum + sentinel
__device__ int                g_chunkseg[MAXC];     // chunk -> containing segment
__device__ unsigned long long g_tden[MAXS];         // fixed-point (2^34) Σ e^t
__device__ unsigned long long g_msum[MAXS];         // fixed-point Σ e^m
__device__ unsigned long long g_dot [MAXS];         // fixed-point Σ e^t * m
__device__ unsigned long long g_acc;                // fixed-point global Σ ce
__device__ unsigned int       g_done;               // finished-block counter (ce)

#define SCALE     17179869184.0   // 2^34
#define INV_SCALE 0x1p-34f        // exact power-of-two

// ============================================================
// Kernel 1: scan + map with ZERO inter-block synchronization.
// Block b redundantly computes sum(scope[0 .. 1024b)) itself
// (<=15 coalesced load rounds, L2-shared), then block-scans its
// own 1024 segments and fills g_off + the chunk->segment map.
// ============================================================
__global__ void __launch_bounds__(1024)
scan_map_kernel(const int* __restrict__ scope, int S, int N)
{
    __shared__ int s_w[32];
    __shared__ int s_pre;

    const int tid  = threadIdx.x;
    const int lane = tid & 31;
    const int wid  = tid >> 5;
    const int b    = blockIdx.x;
    const int s    = b * 1024 + tid;

    // ---- phase 0: redundant sum of all prior tiles ----
    const int P = min(b << 10, S);
    int acc = 0;
    for (int i = tid; i < P; i += 1024) acc += scope[i];   // coalesced

    #pragma unroll
    for (int o = 16; o; o >>= 1) acc += __shfl_xor_sync(0xffffffffu, acc, o);
    if (lane == 0) s_w[wid] = acc;
    __syncthreads();
    if (wid == 0) {
        int v = s_w[lane];   // exactly 32 warps
        #pragma unroll
        for (int o = 16; o; o >>= 1) v += __shfl_xor_sync(0xffffffffu, v, o);
        if (lane == 0) s_pre = v;
    }
    __syncthreads();
    const int pre = s_pre;
    __syncthreads();          // s_w about to be reused

    // ---- phase 1: exclusive scan of own tile ----
    const int len = (s < S) ? scope[s] : 0;

    int x = len;
    #pragma unroll
    for (int off = 1; off < 32; off <<= 1) {
        int y = __shfl_up_sync(0xffffffffu, x, off);
        if (lane >= off) x += y;
    }
    if (lane == 31) s_w[wid] = x;
    __syncthreads();
    if (wid == 0) {
        int w = s_w[lane];
        #pragma unroll
        for (int off = 1; off < 32; off <<= 1) {
            int y = __shfl_up_sync(0xffffffffu, w, off);
            if (lane >= off) w += y;
        }
        s_w[lane] = w;
    }
    __syncthreads();

    const int intra = ((wid == 0) ? 0 : s_w[wid - 1]) + (x - len);

    // ---- phase 2: offsets + chunk map ----
    if (s < S) {
        const int start = pre + intra;
        const int end   = start + len;
        g_off[s] = start;
        if (s == S - 1) g_off[S] = end;    // sentinel (== N)
        for (int c = (start + 255) >> 8; (c << 8) < end; ++c)
            g_chunkseg[c] = s;
    }
}

// ============================================================
// Kernel 2: one WARP per 256-element chunk (balanced single pass).
// NO tail, NO fences, NO single-address atomics — keep it pure.
// ============================================================
__global__ void __launch_bounds__(256)
main_kernel(const float* __restrict__ means,
            const float* __restrict__ targets,
            int N, int S)
{
    const int lane = threadIdx.x & 31;
    const int warp = (blockIdx.x * 256 + threadIdx.x) >> 5;
    const int base = warp * 256;
    if (base >= N) return;

    int s = g_chunkseg[warp];   // 1 load replaces binary search

    const int pos0 = base + lane * 4;
    const int pos1 = base + 128 + lane * 4;

    float e[8], w[8], d[8];
    if (base + 256 <= N) {
        const float4* tp = reinterpret_cast<const float4*>(targets);
        const float4* mp = reinterpret_cast<const float4*>(means);
        const int q = (base >> 2) + lane;
        float4 t0 = tp[q];        float4 t1 = tp[q + 32];
        float4 m0 = mp[q];        float4 m1 = mp[q + 32];
        float tt[8] = {t0.x,t0.y,t0.z,t0.w, t1.x,t1.y,t1.z,t1.w};
        float mm[8] = {m0.x,m0.y,m0.z,m0.w, m1.x,m1.y,m1.z,m1.w};
        #pragma unroll
        for (int j = 0; j < 8; ++j) {
            e[j] = __expf(tt[j]);
            w[j] = __expf(mm[j]);
            d[j] = e[j] * mm[j];
        }
    } else {
        #pragma unroll
        for (int j = 0; j < 8; ++j) {
            int p = (j < 4) ? (pos0 + j) : (pos1 + j - 4);
            float tv = (p < N) ? targets[p] : 0.f;
            float mv = (p < N) ? means[p]   : 0.f;
            e[j] = __expf(tv);
            w[j] = __expf(mv);
            d[j] = e[j] * mv;
        }
    }

    const int last = min(base + 255, N - 1);
    int lower = g_off[s];
    for (;;) {
        const int next = g_off[s + 1];  // sentinel guarantees validity
        float a = 0.f, b = 0.f, c = 0.f;
        #pragma unroll
        for (int j = 0; j < 8; ++j) {
            const int p = (j < 4) ? (pos0 + j) : (pos1 + j - 4);
            if (p >= lower && p < next) { a += e[j]; b += w[j]; c += d[j]; }
        }
        #pragma unroll
        for (int o = 16; o; o >>= 1) {
            a += __shfl_xor_sync(0xffffffffu, a, o);
            b += __shfl_xor_sync(0xffffffffu, b, o);
            c += __shfl_xor_sync(0xffffffffu, c, o);
        }
        if (lane == 0) {
            atomicAdd(&g_tden[s], (unsigned long long)__double2ll_rn((double)a * SCALE));
            atomicAdd(&g_msum[s], (unsigned long long)__double2ll_rn((double)b * SCALE));
            atomicAdd(&g_dot [s], (unsigned long long)__double2ll_rn((double)c * SCALE));
        }
        if (next > last) break;
        lower = next;
        ++s;
    }
}

// ============================================================
// Kernel 3: per-segment CE (fp32) + deterministic reduce + reset
// ============================================================
__global__ void __launch_bounds__(256)
ce_kernel(float* __restrict__ out, int S)
{
    const int tid  = threadIdx.x;
    const int lane = tid & 31;
    const int wid  = tid >> 5;
    const int seg  = blockIdx.x * 256 + tid;

    float ce = 0.f;
    if (seg < S) {
        long long tdq = (long long)g_tden[seg];
        float td = __ll2float_rn(tdq);                                 // 2^34 scale cancels
        float ms = __ll2float_rn((long long)g_msum[seg]) * INV_SCALE;  // exact pow2 scale
        float dt = __ll2float_rn((long long)g_dot [seg]);
        if (tdq > 0) ce = dt / td - __logf(ms);
        g_tden[seg] = 0ull; g_msum[seg] = 0ull; g_dot[seg] = 0ull;     // reset for next replay
    }

    __shared__ float sm[8];
    float v = ce;
    #pragma unroll
    for (int o = 16; o; o >>= 1) v += __shfl_xor_sync(0xffffffffu, v, o);
    if (lane == 0) sm[wid] = v;
    __syncthreads();
    if (wid == 0) {
        v = (lane < 8) ? sm[lane] : 0.f;
        #pragma unroll
        for (int o = 4; o; o >>= 1) v += __shfl_xor_sync(0xffffffffu, v, o);
        if (lane == 0) {
            atomicAdd(&g_acc, (unsigned long long)__double2ll_rn((double)v * SCALE));
            __threadfence();
            unsigned int prev = atomicAdd(&g_done, 1u);
            if (prev == gridDim.x - 1) {
                unsigned long long tot = atomicAdd(&g_acc, 0ull);
                double sum = (double)(long long)tot / SCALE;
                out[0] = (float)(-sum / (double)S);
                g_acc  = 0ull;   // reset for next replay
                g_done = 0u;
                __threadfence();
            }
        }
    }
}

// ============================================================
extern "C" void kernel_launch(void* const* d_in, const int* in_sizes, int n_in,
                              void* d_out, int out_size)
{
    const float* means   = (const float*)d_in[0];
    const int*   scope   = (const int*)  d_in[1];
    const float* targets = (const float*)d_in[2];
    const int N = in_sizes[0];
    const int S = in_sizes[1];

    const int scanBlocks = (S + 1023) / 1024;
    scan_map_kernel<<<scanBlocks, 1024>>>(scope, S, N);

    const int nWarps  = (N + 255) / 256;
    const int nBlocks = (nWarps + 7) / 8;
    main_kernel<<<nBlocks, 256>>>(means, targets, N, S);

    ce_kernel<<<(S + 255) / 256, 256>>>((float*)d_out, S);
}